// round 11
// baseline (speedup 1.0000x reference)
#include <cuda_runtime.h>
#include <cuda_bf16.h>
#include <cstdint>
#include <cstddef>

// ---------------- problem constants ----------------
#define NUM_K 512
#define DIM   64
#define T_LEN 8192
#define B_LEN 32

#define MT    128
#define NTH   256
#define NCTA  2048                 // (B*T)/MT
#define CAP   12                   // per-row candidate cap
#define WLCAP 2048                 // worklist entries

// Output layout: [quantized B*D*T][loss 1][indices as float B*T]
#define LOSS_OFF ((size_t)B_LEN * DIM * T_LEN)
#define IDX_OFF  (LOSS_OFF + 1)

// ---------------- smem layout (bytes) ----------------
#define SM_X     0                 // fp32 [64][128]                 32768
#define SM_SEE   32768             // fp32 [512]                      2048
#define SM_C     34816             // fp32 [128]                       512
#define SM_W     35328             // fp32 [128]                       512
#define SM_XX    35840             // fp32 [128]                       512
#define SM_TH    36352             // fp32 [128]                       512
#define SM_SCNT  36864             // int  [128]                       512
#define SM_SCAND 37376             // u16  [128][CAP]                 3072
#define SM_WL    40448             // u16  [WLCAP]                    4096
#define SM_WLC   44544             // int wlcnt, int gflag              64
#define SM_REDW  44608             // fp32 [8]                          64
#define SM_SIDX  44672             // int  [128]                       512
#define SM_RV    45184             // fp32 [2][128]                   1024
#define SM_RK    46208             // int  [2][128]                   1024
#define SM_ARENA 47232
#define EP_OFF   0                 //   int  [512][16]                32768
#define X8_OFF   32768             //   int  [16][128]                 8192
#define BM_OFF   40960             //   bf16 [128][66]                16896
#define CSTG_OFF 0                 //   alias after refine: fp32[128][65] = 33280
#define SMEM_BYTES (SM_ARENA + 40960 + 16896)   // 105088 -> 2 CTAs/SM

__device__ double   g_partial[NCTA];
__device__ float    g_ee[NUM_K];
__device__ float    g_se;
__device__ float    g_l1e;
__device__ uint32_t g_epack[NUM_K * 16];

__device__ __forceinline__ int dp4a_s8(int a, int b, int c) {
    int r;
    asm("dp4a.s32.s32 %0, %1, %2, %3;" : "=r"(r) : "r"(a), "r"(b), "r"(c));
    return r;
}

// ---------------------------------------------------------------------------
// Prep: smem-staged exact ee, global scales, int8 pack. 1 block x 512 thr.
// ---------------------------------------------------------------------------
__global__ void vq_prep(const float* __restrict__ emb) {
    extern __shared__ float es[];              // [512][65]
    __shared__ float redmx[16], redl1[16], sgmx[1];
    const int tid = threadIdx.x;
    const int lane = tid & 31, wid = tid >> 5;

#pragma unroll
    for (int it = 0; it < 16; it++) {
        int i = tid + it * 512;                // float4 index
        int k = i >> 4, q = i & 15;
        float4 v = __ldg((const float4*)(emb + k * DIM + q * 4));
        float* row = es + k * 65 + q * 4;
        row[0] = v.x; row[1] = v.y; row[2] = v.z; row[3] = v.w;
    }
    __syncthreads();

    const float* er = es + tid * 65;
    float ee = 0.f, l1 = 0.f, mx = 0.f;
#pragma unroll
    for (int d = 0; d < DIM; d++) {
        float e = er[d];
        ee = fmaf(e, e, ee);                   // exact sequential chain
        float a = fabsf(e);
        l1 += a;
        mx = fmaxf(mx, a);
    }
    g_ee[tid] = ee;

#pragma unroll
    for (int off = 16; off; off >>= 1) {
        mx = fmaxf(mx, __shfl_xor_sync(0xffffffffu, mx, off));
        l1 = fmaxf(l1, __shfl_xor_sync(0xffffffffu, l1, off));
    }
    if (lane == 0) { redmx[wid] = mx; redl1[wid] = l1; }
    __syncthreads();
    if (tid == 0) {
        float gm = 0.f, gl = 0.f;
        for (int w = 0; w < 16; w++) {
            gm = fmaxf(gm, redmx[w]);
            gl = fmaxf(gl, redl1[w]);
        }
        sgmx[0] = gm;
        g_l1e   = gl;
        g_se    = gm / 127.0f;
    }
    __syncthreads();
    const float gmx = sgmx[0];
    float inv = (gmx > 0.f) ? (127.0f / gmx) : 0.f;
#pragma unroll
    for (int dq = 0; dq < 16; dq++) {
        uint32_t w = 0;
#pragma unroll
        for (int r = 0; r < 4; r++) {
            int q = __float2int_rn(er[dq * 4 + r] * inv);
            q = max(-127, min(127, q));
            w |= ((uint32_t)q & 0xFFu) << (r * 8);
        }
        g_epack[tid * 16 + dq] = w;
    }
}

// ---------------------------------------------------------------------------
__global__ void __launch_bounds__(NTH, 2)
vq_main(const float* __restrict__ inp, const float* __restrict__ emb,
        float* __restrict__ out) {
    extern __shared__ char smem[];
    float*     X     = (float*)(smem + SM_X);
    float*     see   = (float*)(smem + SM_SEE);
    float*     svC   = (float*)(smem + SM_C);
    float*     svW   = (float*)(smem + SM_W);
    float*     svXX  = (float*)(smem + SM_XX);
    float*     svTH  = (float*)(smem + SM_TH);
    int*       scnt  = (int*)(smem + SM_SCNT);
    uint16_t*  scand = (uint16_t*)(smem + SM_SCAND);
    uint16_t*  wl    = (uint16_t*)(smem + SM_WL);
    int*       wlc   = (int*)(smem + SM_WLC);        // [0]=count [1]=gflag
    float*     redw  = (float*)(smem + SM_REDW);
    int*       sidx  = (int*)(smem + SM_SIDX);
    float*     rv    = (float*)(smem + SM_RV);
    int*       rk    = (int*)(smem + SM_RK);
    int*       EP    = (int*)(smem + SM_ARENA + EP_OFF);
    int*       X8    = (int*)(smem + SM_ARENA + X8_OFF);
    uint16_t*  BM    = (uint16_t*)(smem + SM_ARENA + BM_OFF);
    float*     CSTG  = (float*)(smem + SM_ARENA + CSTG_OFF);

    const int tid  = threadIdx.x;
    const int wid  = tid >> 5;
    const int lane = tid & 31;

    const int b  = blockIdx.x >> 6;             // 64 tiles of 128 per batch
    const int t0 = (blockIdx.x & 63) * MT;
    const float* xbase = inp + (size_t)b * DIM * T_LEN + t0;

    if (tid < MT) scnt[tid] = 0;
    if (tid == 0) { wlc[0] = 0; wlc[1] = 0; }

    // ---- fills: X fp32, EP int8 words, see ----
#pragma unroll
    for (int it = 0; it < 8; it++) {
        int i = tid + it * NTH;
        int d = i >> 5, c = i & 31;
        float4 v = *(const float4*)(xbase + (size_t)d * T_LEN + c * 4);
        *(float4*)(X + d * MT + c * 4) = v;
    }
#pragma unroll
    for (int it = 0; it < 8; it++) {            // 2048 uint4
        int i = tid + it * NTH;
        ((uint4*)EP)[i] = ((const uint4*)g_epack)[i];
    }
#pragma unroll
    for (int it = 0; it < 2; it++) see[tid + it * NTH] = g_ee[tid + it * NTH];
    __syncthreads();

    const float se  = g_se;
    const float l1e = g_l1e;

    // ---- per-vector stats + int8 pack (thread m = tid < 128) ----
    if (tid < MT) {
        const int m = tid;
        float mx = 0.f, xx = 0.f;
#pragma unroll
        for (int d = 0; d < DIM; d++) {
            float v = X[d * MT + m];
            xx = fmaf(v, v, xx);                // exact sequential |x|^2
            mx = fmaxf(mx, fabsf(v));
        }
        float sx  = mx / 127.0f;
        float inv = (mx > 0.f) ? (127.0f / mx) : 0.f;
        int   l1q = 0;
#pragma unroll
        for (int dq = 0; dq < 16; dq++) {
            uint32_t w = 0;
#pragma unroll
            for (int r = 0; r < 4; r++) {
                int q = __float2int_rn(X[(dq * 4 + r) * MT + m] * inv);
                q = max(-127, min(127, q));
                l1q += abs(q);
                w |= ((uint32_t)q & 0xFFu) << (r * 8);
            }
            X8[dq * MT + m] = (int)w;
        }
        svXX[m] = xx;
        svC[m]  = -2.0f * sx * se;
        float Eb = 0.5f * sx * (l1e * 1.0001f + se * (float)l1q);
        svW[m]  = 4.2f * Eb + 5.0e-4f;          // rigorous capture window
    }
    __syncthreads();

    // ---- pass 1: dp4a filter; per-8-code block minima (bf16-RD) ----
    {
        float c[4];
#pragma unroll
        for (int j = 0; j < 4; j++) c[j] = svC[lane + 32 * j];

#pragma unroll 2
        for (int pass = 0; pass < 8; pass++) {
            const int kbase = wid * 64 + pass * 8;
            const int blk   = wid * 8 + pass;
            int acc[4][8];
#pragma unroll
            for (int j = 0; j < 4; j++)
#pragma unroll
                for (int kk = 0; kk < 8; kk++) acc[j][kk] = 0;

#pragma unroll 4
            for (int dq = 0; dq < 16; dq++) {
                int xw[4], ew[8];
#pragma unroll
                for (int j = 0; j < 4; j++) xw[j] = X8[dq * MT + lane + 32 * j];
#pragma unroll
                for (int kk = 0; kk < 8; kk++) ew[kk] = EP[(kbase + kk) * 16 + dq];
#pragma unroll
                for (int j = 0; j < 4; j++)
#pragma unroll
                    for (int kk = 0; kk < 8; kk++)
                        acc[j][kk] = dp4a_s8(xw[j], ew[kk], acc[j][kk]);
            }
            float bmin[4] = {3.4e38f, 3.4e38f, 3.4e38f, 3.4e38f};
#pragma unroll
            for (int kk = 0; kk < 8; kk++) {
                float eek = see[kbase + kk];
#pragma unroll
                for (int j = 0; j < 4; j++) {
                    float s = fmaf(c[j], (float)acc[j][kk], eek);
                    bmin[j] = fminf(bmin[j], s);
                }
            }
#pragma unroll
            for (int j = 0; j < 4; j++) {
                __nv_bfloat16 h = __float2bfloat16_rd(bmin[j]);
                BM[(lane + 32 * j) * 66 + blk] = *(uint16_t*)&h;
            }
        }
    }
    __syncthreads();

    // ---- row thresholds + block worklist (thread m = tid < 128) ----
    if (tid < MT) {
        const int m = tid;
        float mn = 3.4e38f;
#pragma unroll 8
        for (int bk = 0; bk < 64; bk++) {
            uint32_t u = (uint32_t)BM[m * 66 + bk] << 16;
            mn = fminf(mn, __uint_as_float(u));
        }
        float th = mn + svW[m];
        svTH[m] = th;
#pragma unroll 8
        for (int bk = 0; bk < 64; bk++) {
            uint32_t u = (uint32_t)BM[m * 66 + bk] << 16;
            if (__uint_as_float(u) <= th) {
                int pos = atomicAdd(wlc, 1);
                if (pos < WLCAP) wl[pos] = (uint16_t)((m << 6) | bk);
                else             wlc[1] = 1;
            }
        }
    }
    __syncthreads();

    // ---- pass 2: rescan flagged blocks only (int dot identical) ----
    {
        int n = wlc[0]; if (n > WLCAP) n = WLCAP;
        for (int e = wid; e < n; e += 8) {
            int ent = wl[e];
            int m = ent >> 6, bk = ent & 63;
            if (lane < 8) {
                int k = bk * 8 + lane;
                int acc = 0;
#pragma unroll
                for (int dq = 0; dq < 16; dq++)
                    acc = dp4a_s8(X8[dq * MT + m], EP[k * 16 + dq], acc);
                float s = fmaf(svC[m], (float)acc, see[k]);
                if (s <= svTH[m]) {
                    int sl = atomicAdd(&scnt[m], 1);
                    if (sl < CAP) scand[m * CAP + sl] = (uint16_t)k;
                }
            }
        }
    }
    __syncthreads();

    // ---- exact refine (bit-identical chain), 2 threads per row;
    //      emb rows prefetched from L2 via float4 (values identical) ----
    {
        const int m    = tid & 127;
        const int part = tid >> 7;
        const int cnt  = scnt[m];
        const float xx = svXX[m];
        float bv = 3.4e38f;
        int   bk = 0x7fffffff;
        if (!wlc[1] && cnt <= CAP) {
            for (int i = part; i < cnt; i += 2) {
                int k = scand[m * CAP + i];
                float ev[DIM];
#pragma unroll
                for (int q = 0; q < 16; q++) {
                    float4 v = __ldg((const float4*)(emb + k * DIM) + q);
                    ev[4 * q + 0] = v.x; ev[4 * q + 1] = v.y;
                    ev[4 * q + 2] = v.z; ev[4 * q + 3] = v.w;
                }
                float s = 0.f;
#pragma unroll
                for (int d = 0; d < DIM; d++) s = fmaf(X[d * MT + m], ev[d], s);
                float dist = fmaf(-2.f, s, xx) + see[k];
                if (dist < bv || (dist == bv && k < bk)) { bv = dist; bk = k; }
            }
        } else if (part == 0) {                 // ~never: exact full scan
            for (int k = 0; k < NUM_K; k++) {
                float ev[DIM];
#pragma unroll
                for (int q = 0; q < 16; q++) {
                    float4 v = __ldg((const float4*)(emb + k * DIM) + q);
                    ev[4 * q + 0] = v.x; ev[4 * q + 1] = v.y;
                    ev[4 * q + 2] = v.z; ev[4 * q + 3] = v.w;
                }
                float s = 0.f;
#pragma unroll
                for (int d = 0; d < DIM; d++) s = fmaf(X[d * MT + m], ev[d], s);
                float dist = fmaf(-2.f, s, xx) + see[k];
                if (dist < bv) { bv = dist; bk = k; }
            }
        }
        rv[part * MT + m] = bv;
        rk[part * MT + m] = bk;
    }
    __syncthreads();
    if (tid < MT) {
        float v0 = rv[tid], v1 = rv[MT + tid];
        int   k0 = rk[tid], k1 = rk[MT + tid];
        int bi = (v1 < v0 || (v1 == v0 && k1 < k0)) ? k1 : k0;
        sidx[tid] = bi;
        out[IDX_OFF + (size_t)b * T_LEN + t0 + tid] = (float)bi;
    }
    __syncthreads();

    // ---- stage chosen rows into CSTG (EP/X8/BM dead) ----
    for (int m = wid; m < MT; m += 8) {
        int k = sidx[m];
        float2 v = __ldg((const float2*)(emb + k * DIM) + lane);
        CSTG[m * 65 + 2 * lane + 0] = v.x;
        CSTG[m * 65 + 2 * lane + 1] = v.y;
    }
    __syncthreads();

    // ---- quantized write (gather from CSTG) + loss partial ----
    float* qbase = out + (size_t)b * DIM * T_LEN + t0;
    float lacc = 0.f;
#pragma unroll
    for (int it = 0; it < 8; it++) {
        int i = tid + it * NTH;
        int d = i >> 5, c = i & 31;
        int m0 = c * 4;
        float4 q;
        q.x = CSTG[(m0 + 0) * 65 + d];
        q.y = CSTG[(m0 + 1) * 65 + d];
        q.z = CSTG[(m0 + 2) * 65 + d];
        q.w = CSTG[(m0 + 3) * 65 + d];
        *(float4*)(qbase + (size_t)d * T_LEN + m0) = q;
        const float* xr = X + d * MT;
        float dx;
        dx = q.x - xr[m0 + 0]; lacc = fmaf(dx, dx, lacc);
        dx = q.y - xr[m0 + 1]; lacc = fmaf(dx, dx, lacc);
        dx = q.z - xr[m0 + 2]; lacc = fmaf(dx, dx, lacc);
        dx = q.w - xr[m0 + 3]; lacc = fmaf(dx, dx, lacc);
    }
#pragma unroll
    for (int off = 16; off; off >>= 1)
        lacc += __shfl_xor_sync(0xffffffffu, lacc, off);
    if (lane == 0) redw[wid] = lacc;
    __syncthreads();
    if (tid == 0) {
        double s = 0.0;
#pragma unroll
        for (int w = 0; w < 8; w++) s += (double)redw[w];
        g_partial[blockIdx.x] = s;
    }
}

// ---------------------------------------------------------------------------
__global__ void vq_loss(float* __restrict__ out) {
    int lane = threadIdx.x;                     // 32 threads
    double s = 0.0;
    for (int i = 0; i < NCTA / 32; i++)
        s += g_partial[lane * (NCTA / 32) + i];
#pragma unroll
    for (int off = 16; off; off >>= 1)
        s += __shfl_xor_sync(0xffffffffu, s, off);
    if (lane == 0)
        out[LOSS_OFF] = (float)(s * (1.25 / (double)((size_t)B_LEN * DIM * T_LEN)));
}

// ---------------------------------------------------------------------------
extern "C" void kernel_launch(void* const* d_in, const int* in_sizes, int n_in,
                              void* d_out, int out_size) {
    const float* inp = (const float*)d_in[0];   // [32, 64, 8192] f32
    const float* emb = (const float*)d_in[1];   // [512, 64] f32
    float* out = (float*)d_out;

    cudaFuncSetAttribute(vq_prep, cudaFuncAttributeMaxDynamicSharedMemorySize,
                         512 * 65 * 4);
    cudaFuncSetAttribute(vq_main, cudaFuncAttributeMaxDynamicSharedMemorySize,
                         SMEM_BYTES);
    vq_prep<<<1, NUM_K, 512 * 65 * 4>>>(emb);
    vq_main<<<NCTA, NTH, SMEM_BYTES>>>(inp, emb, out);
    vq_loss<<<1, 32>>>(out);
}

// round 14
// speedup vs baseline: 1.1634x; 1.1634x over previous
#include <cuda_runtime.h>
#include <cstdint>
#include <cstddef>

// ---------------- problem constants ----------------
#define NUM_K 512
#define DIM   64
#define T_LEN 8192
#define B_LEN 32

#define MT    256
#define NTH   256
#define NCTA  1024                  // (B*T)/MT
#define NTY   4                     // code split: ty handles codes [ty*128, +128)
#define KPP   8                     // codes per pass per ty
#define NPASS 16                    // 128/KPP

#define SLAB_ULL (NTY * KPP * 65)   // 2080 ull per pass (65 = 64 d + 1 pad)
#define PRE_N    9                  // ceil(2080/256)

// Output layout: [quantized B*D*T][loss 1][indices as float B*T]
#define LOSS_OFF ((size_t)B_LEN * DIM * T_LEN)
#define IDX_OFF  (LOSS_OFF + 1)

// ---------------- smem layout (bytes) ----------------
#define SM_X     0                  // fp32 [64][256]                 65536
#define SM_BUF   65536              // ull slab x2                    33280
#define SM_SEE   98816              // fp32 [512]                      2048
#define SM_REDV  100864             // fp32 [4][256]                   4096
#define SM_REDI  104960             // int  [4][256]                   4096
#define SM_SIDX  109056             // int  [256]                      1024
#define SM_REDW  110080             // fp32 [8] (+pad)                   64
#define SMEM_BYTES 110144           // x2 = 220288 -> 2 CTAs/SM

typedef unsigned long long ull;

__device__ double g_partial[NCTA];
__device__ float  g_ee[NUM_K];
__device__ ull    g_slab[NPASS * SLAB_ULL];   // duplicated (e,e) pass slabs

__device__ __forceinline__ void fma2(ull &acc, ull a, ull b) {
    asm("fma.rn.f32x2 %0, %1, %2, %0;" : "+l"(acc) : "l"(a), "l"(b));
}
__device__ __forceinline__ float2 unpack2(ull v) {
    float2 r;
    asm("mov.b64 {%0, %1}, %2;" : "=f"(r.x), "=f"(r.y) : "l"(v));
    return r;
}
__device__ __forceinline__ ull dup2(float x) {
    ull r;
    asm("mov.b64 %0, {%1, %1};" : "=l"(r) : "f"(x));
    return r;
}

// ---------------------------------------------------------------------------
// Prep: exact ee (sequential chain) + duplicated-lane slab pack.
// 1 block x 512 threads; thread = one code. Reg-capped via launch bounds.
// ---------------------------------------------------------------------------
__global__ void __launch_bounds__(512)
vq_prep(const float* __restrict__ emb) {
    extern __shared__ float es[];               // [512][65]
    const int tid = threadIdx.x;

#pragma unroll
    for (int it = 0; it < 16; it++) {
        int i = tid + it * 512;                 // float4 index
        int k = i >> 4, q = i & 15;
        float4 v = __ldg((const float4*)(emb + k * DIM + q * 4));
        float* row = es + k * 65 + q * 4;
        row[0] = v.x; row[1] = v.y; row[2] = v.z; row[3] = v.w;
    }
    __syncthreads();

    const float* er = es + tid * 65;
    float ee = 0.f;
#pragma unroll
    for (int d = 0; d < DIM; d++) ee = fmaf(er[d], er[d], ee);   // exact chain
    g_ee[tid] = ee;

    // slab position: code c = ty*128 + pass*8 + kk
    const int c = tid;
    const int ty = c >> 7, rem = c & 127;
    const int pass = rem >> 3, kk = rem & 7;
    ull* dst = g_slab + (size_t)pass * SLAB_ULL + (ty * KPP + kk) * 65;
#pragma unroll 8
    for (int d = 0; d < DIM; d++) dst[d] = dup2(er[d]);
}

// ---------------------------------------------------------------------------
__global__ void __launch_bounds__(NTH, 2)
vq_main(const float* __restrict__ inp, const float* __restrict__ emb,
        float* __restrict__ out) {
    extern __shared__ char smem[];
    float* X    = (float*)(smem + SM_X);
    ull*   BUF  = (ull*)(smem + SM_BUF);
    float* see  = (float*)(smem + SM_SEE);
    float* redv = (float*)(smem + SM_REDV);
    int*   redi = (int*)(smem + SM_REDI);
    int*   sidx = (int*)(smem + SM_SIDX);
    float* redw = (float*)(smem + SM_REDW);

    const int tid  = threadIdx.x;
    const int wid  = tid >> 5;
    const int lane = tid & 31;
    const int tx   = tid & 63;                 // vector-pair base
    const int ty   = tid >> 6;                 // code group

    const int b  = blockIdx.x >> 5;            // 32 tiles of 256 per batch
    const int t0 = (blockIdx.x & 31) * MT;
    const float* xbase = inp + (size_t)b * DIM * T_LEN + t0;

    // ---- fills: X fp32 [64][256] (coalesced), see ----
#pragma unroll
    for (int it = 0; it < 16; it++) {
        int i = tid + it * NTH;
        int d = i >> 6, c = i & 63;
        float4 v = *(const float4*)(xbase + (size_t)d * T_LEN + c * 4);
        *(float4*)(X + d * MT + c * 4) = v;
    }
#pragma unroll
    for (int it = 0; it < 2; it++) see[tid + it * NTH] = g_ee[tid + it * NTH];

    // ---- preload slab 0 into buffer 0 ----
    ull pre[PRE_N];
#pragma unroll
    for (int i = 0; i < PRE_N; i++) {
        int idx = tid + i * NTH;
        if (idx < SLAB_ULL) pre[i] = g_slab[idx];
    }
#pragma unroll
    for (int i = 0; i < PRE_N; i++) {
        int idx = tid + i * NTH;
        if (idx < SLAB_ULL) BUF[idx] = pre[i];
    }
    __syncthreads();

    // ---- exact |x|^2 for this thread's 4 vectors (sequential chains) ----
    // vectors: 2tx, 2tx+1, 2tx+128, 2tx+129
    float xx[4] = {0.f, 0.f, 0.f, 0.f};
#pragma unroll
    for (int d = 0; d < DIM; d++) {
        float2 a = *(const float2*)(X + d * MT + 2 * tx);
        float2 c = *(const float2*)(X + d * MT + 2 * tx + 128);
        xx[0] = fmaf(a.x, a.x, xx[0]);
        xx[1] = fmaf(a.y, a.y, xx[1]);
        xx[2] = fmaf(c.x, c.x, xx[2]);
        xx[3] = fmaf(c.y, c.y, xx[3]);
    }

    float minv[4] = {3.4e38f, 3.4e38f, 3.4e38f, 3.4e38f};
    int   mini[4] = {0, 0, 0, 0};

    // ---- mainloop: 16 passes, double-buffered slabs ----
    for (int pass = 0; pass < NPASS; pass++) {
        const ull* cur = BUF + (pass & 1) * SLAB_ULL + ty * (KPP * 65);

        // prefetch next slab into registers (latency hidden by compute)
        if (pass < NPASS - 1) {
            const ull* gs = g_slab + (size_t)(pass + 1) * SLAB_ULL;
#pragma unroll
            for (int i = 0; i < PRE_N; i++) {
                int idx = tid + i * NTH;
                if (idx < SLAB_ULL) pre[i] = gs[idx];
            }
        }

        ull acc0[KPP], acc1[KPP];
#pragma unroll
        for (int kk = 0; kk < KPP; kk++) { acc0[kk] = 0ull; acc1[kk] = 0ull; }

        // each f32x2 lane = one vector's sequential d-chain (bit-exact)
#pragma unroll 8
        for (int d = 0; d < DIM; d++) {
            ull xv0 = *(const ull*)(X + d * MT + 2 * tx);
            ull xv1 = *(const ull*)(X + d * MT + 2 * tx + 128);
#pragma unroll
            for (int kk = 0; kk < KPP; kk++) {
                ull ev = cur[kk * 65 + d];     // broadcast (e,e)
                fma2(acc0[kk], xv0, ev);
                fma2(acc1[kk], xv1, ev);
            }
        }

        // epilogue: dist = fl(fl(xx - 2*dot) + ee); ascending k, strict <
#pragma unroll
        for (int kk = 0; kk < KPP; kk++) {
            int c = ty * 128 + pass * KPP + kk;
            float eek = see[c];
            float2 p0 = unpack2(acc0[kk]);
            float2 p1 = unpack2(acc1[kk]);
            float d0 = fmaf(-2.f, p0.x, xx[0]) + eek;
            float d1 = fmaf(-2.f, p0.y, xx[1]) + eek;
            float d2 = fmaf(-2.f, p1.x, xx[2]) + eek;
            float d3 = fmaf(-2.f, p1.y, xx[3]) + eek;
            if (d0 < minv[0]) { minv[0] = d0; mini[0] = c; }
            if (d1 < minv[1]) { minv[1] = d1; mini[1] = c; }
            if (d2 < minv[2]) { minv[2] = d2; mini[2] = c; }
            if (d3 < minv[3]) { minv[3] = d3; mini[3] = c; }
        }

        // commit prefetched slab to the other buffer
        if (pass < NPASS - 1) {
            ull* nxt = BUF + ((pass + 1) & 1) * SLAB_ULL;
#pragma unroll
            for (int i = 0; i < PRE_N; i++) {
                int idx = tid + i * NTH;
                if (idx < SLAB_ULL) nxt[idx] = pre[i];
            }
        }
        __syncthreads();
    }

    // ---- cross-ty argmin reduction (ty ascending == code ascending) ----
#pragma unroll
    for (int v = 0; v < 4; v++) {
        int m = 2 * tx + (v & 1) + 128 * (v >> 1);
        redv[ty * MT + m] = minv[v];
        redi[ty * MT + m] = mini[v];
    }
    __syncthreads();
    {
        int m = tid;
        float bv = redv[m];
        int   bi = redi[m];
#pragma unroll
        for (int q = 1; q < NTY; q++) {
            float v = redv[q * MT + m];
            if (v < bv) { bv = v; bi = redi[q * MT + m]; }
        }
        sidx[m] = bi;
        out[IDX_OFF + (size_t)b * T_LEN + t0 + m] = (float)bi;
    }

    // ---- quantized write + loss, in 2 staged chunks over dead BUF ----
    float* qbase = out + (size_t)b * DIM * T_LEN + t0;
    float* CST   = (float*)(smem + SM_BUF);     // [128][65] per chunk
    float lacc = 0.f;
#pragma unroll
    for (int chunk = 0; chunk < 2; chunk++) {
        __syncthreads();                        // BUF free / prev chunk done
        for (int r = wid; r < 128; r += 8) {    // stage 128 chosen rows
            int k = sidx[chunk * 128 + r];
            float2 v = __ldg((const float2*)(emb + k * DIM) + lane);
            CST[r * 65 + 2 * lane + 0] = v.x;
            CST[r * 65 + 2 * lane + 1] = v.y;
        }
        __syncthreads();
#pragma unroll
        for (int it = 0; it < 8; it++) {
            int i = tid + it * NTH;
            int d = i >> 5, cc = i & 31;
            int r0 = cc * 4;                    // row within chunk
            int m0 = chunk * 128 + r0;
            float4 q;
            q.x = CST[(r0 + 0) * 65 + d];
            q.y = CST[(r0 + 1) * 65 + d];
            q.z = CST[(r0 + 2) * 65 + d];
            q.w = CST[(r0 + 3) * 65 + d];
            *(float4*)(qbase + (size_t)d * T_LEN + m0) = q;
            const float* xr = X + d * MT + m0;
            float dx;
            dx = q.x - xr[0]; lacc = fmaf(dx, dx, lacc);
            dx = q.y - xr[1]; lacc = fmaf(dx, dx, lacc);
            dx = q.z - xr[2]; lacc = fmaf(dx, dx, lacc);
            dx = q.w - xr[3]; lacc = fmaf(dx, dx, lacc);
        }
    }
#pragma unroll
    for (int off = 16; off; off >>= 1)
        lacc += __shfl_xor_sync(0xffffffffu, lacc, off);
    if (lane == 0) redw[wid] = lacc;
    __syncthreads();
    if (tid == 0) {
        double s = 0.0;
#pragma unroll
        for (int w = 0; w < 8; w++) s += (double)redw[w];
        g_partial[blockIdx.x] = s;
    }
}

// ---------------------------------------------------------------------------
__global__ void __launch_bounds__(32)
vq_loss(float* __restrict__ out) {
    int lane = threadIdx.x;                     // 32 threads
    double s = 0.0;
    for (int i = 0; i < NCTA / 32; i++)
        s += g_partial[lane * (NCTA / 32) + i];
#pragma unroll
    for (int off = 16; off; off >>= 1)
        s += __shfl_xor_sync(0xffffffffu, s, off);
    if (lane == 0)
        out[LOSS_OFF] = (float)(s * (1.25 / (double)((size_t)B_LEN * DIM * T_LEN)));
}

// ---------------------------------------------------------------------------
extern "C" void kernel_launch(void* const* d_in, const int* in_sizes, int n_in,
                              void* d_out, int out_size) {
    const float* inp = (const float*)d_in[0];   // [32, 64, 8192] f32
    const float* emb = (const float*)d_in[1];   // [512, 64] f32
    float* out = (float*)d_out;

    cudaFuncSetAttribute(vq_prep, cudaFuncAttributeMaxDynamicSharedMemorySize,
                         512 * 65 * 4);
    cudaFuncSetAttribute(vq_main, cudaFuncAttributeMaxDynamicSharedMemorySize,
                         SMEM_BYTES);
    vq_prep<<<1, NUM_K, 512 * 65 * 4>>>(emb);
    vq_main<<<NCTA, NTH, SMEM_BYTES>>>(inp, emb, out);
    vq_loss<<<1, 32>>>(out);
}

// round 15
// speedup vs baseline: 1.1729x; 1.0082x over previous
#include <cuda_runtime.h>
#include <cstdint>
#include <cstddef>

// ---------------- problem constants ----------------
#define NUM_K 512
#define DIM   64
#define T_LEN 8192
#define B_LEN 32

#define MT    256
#define NTH   256
#define NCTA  1024                  // (B*T)/MT
#define NTY   4                     // code split: ty handles codes [ty*128, +128)
#define KPP   8                     // codes per pass per ty
#define NPASS 16                    // 128/KPP

#define ROW_ULL  66                 // 64 dup-pairs + 2 pad -> 16B-aligned pairs
#define SLAB_ULL (32 * ROW_ULL)     // 2112 ull per pass slab
#define SLAB_BYTES (SLAB_ULL * 8)   // 16896
#define CP_OPS   (SLAB_BYTES / 16)  // 1056 cp.async.cg ops per slab

// Output layout: [quantized B*D*T][loss 1][indices as float B*T]
#define LOSS_OFF ((size_t)B_LEN * DIM * T_LEN)
#define IDX_OFF  (LOSS_OFF + 1)

// ---------------- smem layout (bytes) ----------------
#define SM_X     0                  // fp32 [64][256]                 65536
#define SM_BUF   65536              // ull slab x2                    33792
#define SM_SEE   99328              // fp32 [512]                      2048
#define SM_REDV  101376             // fp32 [4][256]                   4096
#define SM_REDI  105472             // int  [4][256]                   4096
#define SM_SIDX  109568             // int  [256]                      1024
#define SM_REDW  110592             // fp32 [8] (+pad)                   64
#define SMEM_BYTES 110656           // x2 = 221312 -> 2 CTAs/SM

typedef unsigned long long ull;

__device__ double g_partial[NCTA];
__device__ float  g_ee[NUM_K];
__device__ ull    g_slab[NPASS * SLAB_ULL];   // duplicated (e,e) pass slabs

__device__ __forceinline__ void fma2(ull &acc, ull a, ull b) {
    asm("fma.rn.f32x2 %0, %1, %2, %0;" : "+l"(acc) : "l"(a), "l"(b));
}
__device__ __forceinline__ float2 unpack2(ull v) {
    float2 r;
    asm("mov.b64 {%0, %1}, %2;" : "=f"(r.x), "=f"(r.y) : "l"(v));
    return r;
}
__device__ __forceinline__ ull dup2(float x) {
    ull r;
    asm("mov.b64 %0, {%1, %1};" : "=l"(r) : "f"(x));
    return r;
}
__device__ __forceinline__ uint32_t smem_u32(const void* p) {
    uint32_t a;
    asm("{ .reg .u64 t; cvta.to.shared.u64 t, %1; cvt.u32.u64 %0, t; }"
        : "=r"(a) : "l"(p));
    return a;
}
__device__ __forceinline__ void cp16(uint32_t s, const void* g) {
    asm volatile("cp.async.cg.shared.global [%0], [%1], 16;"
                 :: "r"(s), "l"(g) : "memory");
}
__device__ __forceinline__ void cp_commit() {
    asm volatile("cp.async.commit_group;" ::: "memory");
}
__device__ __forceinline__ void cp_wait0() {
    asm volatile("cp.async.wait_group 0;" ::: "memory");
}

// ---------------------------------------------------------------------------
// Prep: exact ee (sequential chain) + duplicated-lane slab pack (pitch 66).
// 1 block x 512 threads; thread = one code.
// ---------------------------------------------------------------------------
__global__ void __launch_bounds__(512)
vq_prep(const float* __restrict__ emb) {
    extern __shared__ float es[];               // [512][65]
    const int tid = threadIdx.x;

#pragma unroll
    for (int it = 0; it < 16; it++) {
        int i = tid + it * 512;                 // float4 index
        int k = i >> 4, q = i & 15;
        float4 v = __ldg((const float4*)(emb + k * DIM + q * 4));
        float* row = es + k * 65 + q * 4;
        row[0] = v.x; row[1] = v.y; row[2] = v.z; row[3] = v.w;
    }
    __syncthreads();

    const float* er = es + tid * 65;
    float ee = 0.f;
#pragma unroll
    for (int d = 0; d < DIM; d++) ee = fmaf(er[d], er[d], ee);   // exact chain
    g_ee[tid] = ee;

    // slab position: code c = ty*128 + pass*8 + kk -> row (ty*8+kk) of slab[pass]
    const int c = tid;
    const int ty = c >> 7, rem = c & 127;
    const int pass = rem >> 3, kk = rem & 7;
    ull* dst = g_slab + (size_t)pass * SLAB_ULL + (ty * KPP + kk) * ROW_ULL;
#pragma unroll 8
    for (int d = 0; d < DIM; d++) dst[d] = dup2(er[d]);
    dst[64] = 0ull; dst[65] = 0ull;
}

// ---------------------------------------------------------------------------
__global__ void __launch_bounds__(NTH, 2)
vq_main(const float* __restrict__ inp, const float* __restrict__ emb,
        float* __restrict__ out) {
    extern __shared__ char smem[];
    float* X    = (float*)(smem + SM_X);
    ull*   BUF  = (ull*)(smem + SM_BUF);
    float* see  = (float*)(smem + SM_SEE);
    float* redv = (float*)(smem + SM_REDV);
    int*   redi = (int*)(smem + SM_REDI);
    int*   sidx = (int*)(smem + SM_SIDX);
    float* redw = (float*)(smem + SM_REDW);

    const int tid  = threadIdx.x;
    const int wid  = tid >> 5;
    const int lane = tid & 31;
    const int tx   = tid & 63;                 // vector-pair base
    const int ty   = tid >> 6;                 // code group

    const int b  = blockIdx.x >> 5;            // 32 tiles of 256 per batch
    const int t0 = (blockIdx.x & 31) * MT;
    const float* xbase = inp + (size_t)b * DIM * T_LEN + t0;

    const uint32_t buf_u32 = smem_u32(BUF);

    // ---- kick slab 0 via cp.async (overlaps the X fill below) ----
    for (int i = tid; i < CP_OPS; i += NTH)
        cp16(buf_u32 + i * 16, (const char*)g_slab + i * 16);
    cp_commit();

    // ---- fills: X fp32 [64][256] (coalesced), see ----
#pragma unroll
    for (int it = 0; it < 16; it++) {
        int i = tid + it * NTH;
        int d = i >> 6, c = i & 63;
        float4 v = *(const float4*)(xbase + (size_t)d * T_LEN + c * 4);
        *(float4*)(X + d * MT + c * 4) = v;
    }
#pragma unroll
    for (int it = 0; it < 2; it++) see[tid + it * NTH] = g_ee[tid + it * NTH];
    cp_wait0();
    __syncthreads();

    // ---- exact |x|^2 for this thread's 4 vectors (sequential chains) ----
    // vectors: 2tx, 2tx+1, 2tx+128, 2tx+129
    float xx[4] = {0.f, 0.f, 0.f, 0.f};
#pragma unroll
    for (int d = 0; d < DIM; d++) {
        float2 a = *(const float2*)(X + d * MT + 2 * tx);
        float2 c = *(const float2*)(X + d * MT + 2 * tx + 128);
        xx[0] = fmaf(a.x, a.x, xx[0]);
        xx[1] = fmaf(a.y, a.y, xx[1]);
        xx[2] = fmaf(c.x, c.x, xx[2]);
        xx[3] = fmaf(c.y, c.y, xx[3]);
    }

    float minv[4] = {3.4e38f, 3.4e38f, 3.4e38f, 3.4e38f};
    int   mini[4] = {0, 0, 0, 0};

    // ---- mainloop: 16 passes, cp.async double-buffered slabs ----
    for (int pass = 0; pass < NPASS; pass++) {
        // kick next slab copy (async; lands well before next pass)
        if (pass < NPASS - 1) {
            const char* src = (const char*)(g_slab + (size_t)(pass + 1) * SLAB_ULL);
            uint32_t dst = buf_u32 + ((pass + 1) & 1) * SLAB_BYTES;
            for (int i = tid; i < CP_OPS; i += NTH)
                cp16(dst + i * 16, src + i * 16);
            cp_commit();
        }

        const ull* cur = BUF + (pass & 1) * SLAB_ULL + ty * (KPP * ROW_ULL);

        ull acc0[KPP], acc1[KPP];
#pragma unroll
        for (int kk = 0; kk < KPP; kk++) { acc0[kk] = 0ull; acc1[kk] = 0ull; }

        // paired-d steps: one LDS.128 broadcast fetches (e[d], e[d+1]) dup pairs;
        // each f32x2 lane remains a sequential d-chain (d then d+1) -> bit-exact
#pragma unroll 4
        for (int dp = 0; dp < 32; dp++) {
            const int d = 2 * dp;
            ull xa0 = *(const ull*)(X + d * MT + 2 * tx);
            ull xa1 = *(const ull*)(X + d * MT + 2 * tx + 128);
            ull xb0 = *(const ull*)(X + (d + 1) * MT + 2 * tx);
            ull xb1 = *(const ull*)(X + (d + 1) * MT + 2 * tx + 128);
#pragma unroll
            for (int kk = 0; kk < KPP; kk++) {
                ulonglong2 e2 = *(const ulonglong2*)(cur + kk * ROW_ULL + d);
                fma2(acc0[kk], xa0, e2.x);
                fma2(acc1[kk], xa1, e2.x);
                fma2(acc0[kk], xb0, e2.y);
                fma2(acc1[kk], xb1, e2.y);
            }
        }

        // epilogue: dist = fl(fl(xx - 2*dot) + ee); ascending k, strict <
#pragma unroll
        for (int kk = 0; kk < KPP; kk++) {
            int c = ty * 128 + pass * KPP + kk;
            float eek = see[c];
            float2 p0 = unpack2(acc0[kk]);
            float2 p1 = unpack2(acc1[kk]);
            float d0 = fmaf(-2.f, p0.x, xx[0]) + eek;
            float d1 = fmaf(-2.f, p0.y, xx[1]) + eek;
            float d2 = fmaf(-2.f, p1.x, xx[2]) + eek;
            float d3 = fmaf(-2.f, p1.y, xx[3]) + eek;
            if (d0 < minv[0]) { minv[0] = d0; mini[0] = c; }
            if (d1 < minv[1]) { minv[1] = d1; mini[1] = c; }
            if (d2 < minv[2]) { minv[2] = d2; mini[2] = c; }
            if (d3 < minv[3]) { minv[3] = d3; mini[3] = c; }
        }

        cp_wait0();                  // next slab landed (no-op on last pass)
        __syncthreads();
    }

    // ---- cross-ty argmin reduction (ty ascending == code ascending) ----
#pragma unroll
    for (int v = 0; v < 4; v++) {
        int m = 2 * tx + (v & 1) + 128 * (v >> 1);
        redv[ty * MT + m] = minv[v];
        redi[ty * MT + m] = mini[v];
    }
    __syncthreads();
    {
        int m = tid;
        float bv = redv[m];
        int   bi = redi[m];
#pragma unroll
        for (int q = 1; q < NTY; q++) {
            float v = redv[q * MT + m];
            if (v < bv) { bv = v; bi = redi[q * MT + m]; }
        }
        sidx[m] = bi;
        out[IDX_OFF + (size_t)b * T_LEN + t0 + m] = (float)bi;
    }

    // ---- quantized write + loss, in 2 staged chunks over dead BUF ----
    float* qbase = out + (size_t)b * DIM * T_LEN + t0;
    float* CST   = (float*)(smem + SM_BUF);     // [128][65] per chunk
    float lacc = 0.f;
#pragma unroll
    for (int chunk = 0; chunk < 2; chunk++) {
        __syncthreads();                        // BUF free / prev chunk done
        for (int r = wid; r < 128; r += 8) {    // stage 128 chosen rows
            int k = sidx[chunk * 128 + r];
            float2 v = __ldg((const float2*)(emb + k * DIM) + lane);
            CST[r * 65 + 2 * lane + 0] = v.x;
            CST[r * 65 + 2 * lane + 1] = v.y;
        }
        __syncthreads();
#pragma unroll
        for (int it = 0; it < 8; it++) {
            int i = tid + it * NTH;
            int d = i >> 5, cc = i & 31;
            int r0 = cc * 4;                    // row within chunk
            int m0 = chunk * 128 + r0;
            float4 q;
            q.x = CST[(r0 + 0) * 65 + d];
            q.y = CST[(r0 + 1) * 65 + d];
            q.z = CST[(r0 + 2) * 65 + d];
            q.w = CST[(r0 + 3) * 65 + d];
            *(float4*)(qbase + (size_t)d * T_LEN + m0) = q;
            const float* xr = X + d * MT + m0;
            float dx;
            dx = q.x - xr[0]; lacc = fmaf(dx, dx, lacc);
            dx = q.y - xr[1]; lacc = fmaf(dx, dx, lacc);
            dx = q.z - xr[2]; lacc = fmaf(dx, dx, lacc);
            dx = q.w - xr[3]; lacc = fmaf(dx, dx, lacc);
        }
    }
#pragma unroll
    for (int off = 16; off; off >>= 1)
        lacc += __shfl_xor_sync(0xffffffffu, lacc, off);
    if (lane == 0) redw[wid] = lacc;
    __syncthreads();
    if (tid == 0) {
        double s = 0.0;
#pragma unroll
        for (int w = 0; w < 8; w++) s += (double)redw[w];
        g_partial[blockIdx.x] = s;
    }
}

// ---------------------------------------------------------------------------
__global__ void __launch_bounds__(32)
vq_loss(float* __restrict__ out) {
    int lane = threadIdx.x;                     // 32 threads
    double s = 0.0;
    for (int i = 0; i < NCTA / 32; i++)
        s += g_partial[lane * (NCTA / 32) + i];
#pragma unroll
    for (int off = 16; off; off >>= 1)
        s += __shfl_xor_sync(0xffffffffu, s, off);
    if (lane == 0)
        out[LOSS_OFF] = (float)(s * (1.25 / (double)((size_t)B_LEN * DIM * T_LEN)));
}

// ---------------------------------------------------------------------------
extern "C" void kernel_launch(void* const* d_in, const int* in_sizes, int n_in,
                              void* d_out, int out_size) {
    const float* inp = (const float*)d_in[0];   // [32, 64, 8192] f32
    const float* emb = (const float*)d_in[1];   // [512, 64] f32
    float* out = (float*)d_out;

    cudaFuncSetAttribute(vq_prep, cudaFuncAttributeMaxDynamicSharedMemorySize,
                         512 * 65 * 4);
    cudaFuncSetAttribute(vq_main, cudaFuncAttributeMaxDynamicSharedMemorySize,
                         SMEM_BYTES);
    vq_prep<<<1, NUM_K, 512 * 65 * 4>>>(emb);
    vq_main<<<NCTA, NTH, SMEM_BYTES>>>(inp, emb, out);
    vq_loss<<<1, 32>>>(out);
}